// round 8
// baseline (speedup 1.0000x reference)
#include <cuda_runtime.h>
#include <cuda_fp16.h>
#include <mma.h>
#include <cstdint>
#include <cstddef>

using namespace nvcuda;

// x: [16][32][128][128] fp32 == X[2][256][16384]
// Wq: [512][256], Wkv: [1024][256], Wout: [256][512], bout: [256]
// out: [2][256][16384] fp32
#define NSEQ 16384
#define SMS2 40   // hgemm staging row stride (halves)
#define SIMS 72   // sim/outm attn row stride (halves)

// ------------------------------ scratch ------------------------------------
// __device__ globals referenced ONLY from device code.
__device__ float  g_part[(size_t)16 * 32 * 64 * 64];    // sim partials
__device__ float  g_attn[(size_t)16 * 64 * 64];         // softmax(sim)
__device__ __half g_qk_hi[(size_t)2 * 1024 * 16384];    // Q(0..511),K(512..1023) hi
__device__ __half g_qk_lo[(size_t)2 * 1024 * 16384];
__device__ __half g_v_hi [(size_t)2 * 512 * 16384];     // V hi
__device__ __half g_v_lo [(size_t)2 * 512 * 16384];
__device__ __half g_outmT_hi[(size_t)2 * 16384 * 512];  // (attn@V)^T hi [g][p][c]
__device__ __half g_outmT_lo[(size_t)2 * 16384 * 512];
__device__ __half g_xt_hi[(size_t)2 * 16384 * 256];     // X^T hi [g][n][k]
__device__ __half g_xt_lo[(size_t)2 * 16384 * 256];
__device__ __half g_w_hi [(size_t)1536 * 256];          // [Wq;Wkv] hi
__device__ __half g_w_lo [(size_t)1536 * 256];
__device__ __half g_wout_hi[(size_t)256 * 512];         // Wout hi
__device__ __half g_wout_lo[(size_t)256 * 512];

__device__ __forceinline__ void split_hl(float v, __half& hi, __half& lo) {
    hi = __float2half_rn(v);
    lo = __float2half_rn(v - __half2float(hi));
}

// ---------------------------------------------------------------------------
// Kernel A: weight conversion fp32 -> fp16 hi/lo
// ---------------------------------------------------------------------------
__global__ void convert_w(const float* __restrict__ Wq, const float* __restrict__ Wkv,
                          const float* __restrict__ Wout)
{
    int i = blockIdx.x * 256 + threadIdx.x;
    if (i < 1536 * 256) {
        float v = (i < 512 * 256) ? Wq[i] : Wkv[i - 512 * 256];
        split_hl(v, g_w_hi[i], g_w_lo[i]);
    }
    if (i < 256 * 512) split_hl(Wout[i], g_wout_hi[i], g_wout_lo[i]);
}

// ---------------------------------------------------------------------------
// Kernel B: X [g][256][16384] fp32 -> XT [g][16384][256] fp16 hi/lo
// ---------------------------------------------------------------------------
__global__ void __launch_bounds__(256) convert_x(const float* __restrict__ x)
{
    __shared__ float t[32][33];
    const int g  = blockIdx.z;
    const int n0 = blockIdx.x * 32;
    const int k0 = blockIdx.y * 32;
    const int tx = threadIdx.x, ty = threadIdx.y;
    const float* xg = x + (size_t)g * 256 * NSEQ;
#pragma unroll
    for (int r = 0; r < 32; r += 8)
        t[ty + r][tx] = xg[(size_t)(k0 + ty + r) * NSEQ + n0 + tx];
    __syncthreads();
    __half* hi = g_xt_hi + (size_t)g * NSEQ * 256;
    __half* lo = g_xt_lo + (size_t)g * NSEQ * 256;
#pragma unroll
    for (int r = 0; r < 32; r += 8) {
        const size_t o = (size_t)(n0 + ty + r) * 256 + k0 + tx;
        split_hl(t[tx][ty + r], hi[o], lo[o]);
    }
}

// ---------------------------------------------------------------------------
// hi/lo compensated wmma GEMM body. Block tile 128x128, K-chunk 32,
// 8 warps 2(m) x 4(n). HILO_OUT: epilogue emits fp16 hi/lo (Q/K/V split);
// else fp32 (+bias) direct.
// ---------------------------------------------------------------------------
template <bool HILO_OUT>
__device__ __forceinline__ void hgemm_body(const __half* __restrict__ Ahi,
                                           const __half* __restrict__ Alo,
                                           const __half* __restrict__ Bhi,
                                           const __half* __restrict__ Blo,
                                           float* __restrict__ C,
                                           const float* __restrict__ bias,
                                           int K, size_t b_batch, size_t c_batch)
{
    __shared__ __align__(32) char gsm[49152];
    __half* sAh = reinterpret_cast<__half*>(gsm);
    __half* sAl = sAh + 128 * SMS2;
    __half* sBh = sAl + 128 * SMS2;
    __half* sBl = sBh + 128 * SMS2;
    float*  brep = reinterpret_cast<float*>(gsm + 4 * 128 * SMS2 * 2);  // 8 KB

    const int tid = threadIdx.x;
    const int wid = tid >> 5;
    const int n0 = blockIdx.x * 128;
    const int m0 = blockIdx.y * 128;
    const int g  = blockIdx.z;
    Bhi += (size_t)g * b_batch;
    Blo += (size_t)g * b_batch;

    const int wm = wid >> 2;   // 0..1
    const int wn = wid & 3;    // 0..3

    for (int r = tid; r < 128; r += 256) {
        const float bv = (!HILO_OUT && bias) ? bias[m0 + r] : 0.0f;
#pragma unroll
        for (int c = 0; c < 16; ++c) brep[r * 16 + c] = bv;
    }
    __syncthreads();

    wmma::fragment<wmma::accumulator, 16, 16, 16, float> acc[4][2];
#pragma unroll
    for (int mi = 0; mi < 4; ++mi)
#pragma unroll
        for (int ni = 0; ni < 2; ++ni)
            wmma::load_matrix_sync(acc[mi][ni],
                                   &brep[(wm * 64 + mi * 16) * 16], 16,
                                   wmma::mem_row_major);

#pragma unroll 1
    for (int kk = 0; kk < K; kk += 32) {
        __syncthreads();
#pragma unroll
        for (int it = 0; it < 2; ++it) {
            const int idx = tid + it * 256;       // 0..511
            const int row = idx >> 2;
            const int c4  = idx & 3;
            const size_t goff = (size_t)row * K + kk + c4 * 8;
            const int    soff = row * SMS2 + c4 * 8;
            *reinterpret_cast<uint4*>(&sAh[soff]) =
                *reinterpret_cast<const uint4*>(Ahi + (size_t)m0 * K + goff);
            *reinterpret_cast<uint4*>(&sAl[soff]) =
                *reinterpret_cast<const uint4*>(Alo + (size_t)m0 * K + goff);
            *reinterpret_cast<uint4*>(&sBh[soff]) =
                *reinterpret_cast<const uint4*>(Bhi + (size_t)n0 * K + goff);
            *reinterpret_cast<uint4*>(&sBl[soff]) =
                *reinterpret_cast<const uint4*>(Blo + (size_t)n0 * K + goff);
        }
        __syncthreads();

#pragma unroll
        for (int ks = 0; ks < 2; ++ks) {
            wmma::fragment<wmma::matrix_a, 16, 16, 16, __half, wmma::row_major> fah[4], fal[4];
            wmma::fragment<wmma::matrix_b, 16, 16, 16, __half, wmma::col_major> fbh[2], fbl[2];
#pragma unroll
            for (int mi = 0; mi < 4; ++mi) {
                const int ro = (wm * 64 + mi * 16) * SMS2 + ks * 16;
                wmma::load_matrix_sync(fah[mi], &sAh[ro], SMS2);
                wmma::load_matrix_sync(fal[mi], &sAl[ro], SMS2);
            }
#pragma unroll
            for (int ni = 0; ni < 2; ++ni) {
                const int ro = (wn * 32 + ni * 16) * SMS2 + ks * 16;
                wmma::load_matrix_sync(fbh[ni], &sBh[ro], SMS2);
                wmma::load_matrix_sync(fbl[ni], &sBl[ro], SMS2);
            }
#pragma unroll
            for (int mi = 0; mi < 4; ++mi)
#pragma unroll
                for (int ni = 0; ni < 2; ++ni) {
                    wmma::mma_sync(acc[mi][ni], fah[mi], fbh[ni], acc[mi][ni]);
                    wmma::mma_sync(acc[mi][ni], fah[mi], fbl[ni], acc[mi][ni]);
                    wmma::mma_sync(acc[mi][ni], fal[mi], fbh[ni], acc[mi][ni]);
                }
        }
    }

    if (!HILO_OUT) {
        C += (size_t)g * c_batch;
#pragma unroll
        for (int mi = 0; mi < 4; ++mi)
#pragma unroll
            for (int ni = 0; ni < 2; ++ni)
                wmma::store_matrix_sync(
                    C + (size_t)(m0 + wm * 64 + mi * 16) * NSEQ + n0 + wn * 32 + ni * 16,
                    acc[mi][ni], NSEQ, wmma::mem_row_major);
    } else {
        // emit fp16 hi/lo: Q/K rows (m0 < 1024) -> g_qk, V rows -> g_v
        __half *dh, *dl;
        int mrow;
        if (m0 < 1024) {
            dh = g_qk_hi + (size_t)g * 1024 * NSEQ;
            dl = g_qk_lo + (size_t)g * 1024 * NSEQ;
            mrow = m0;
        } else {
            dh = g_v_hi + (size_t)g * 512 * NSEQ;
            dl = g_v_lo + (size_t)g * 512 * NSEQ;
            mrow = m0 - 1024;
        }
        float* fbuf = reinterpret_cast<float*>(gsm);   // 128 x 64 fp32 = 32 KB
#pragma unroll
        for (int half = 0; half < 2; ++half) {
            __syncthreads();
            if ((wn >> 1) == half) {
#pragma unroll
                for (int mi = 0; mi < 4; ++mi)
#pragma unroll
                    for (int ni = 0; ni < 2; ++ni)
                        wmma::store_matrix_sync(
                            fbuf + (wm * 64 + mi * 16) * 64 + (wn & 1) * 32 + ni * 16,
                            acc[mi][ni], 64, wmma::mem_row_major);
            }
            __syncthreads();
            const int r  = tid >> 1;
            const int c0 = (tid & 1) * 32;
            __half2 hbuf[16], lbuf[16];
#pragma unroll
            for (int q = 0; q < 16; ++q) {
                __half h0, l0, h1, l1;
                split_hl(fbuf[r * 64 + c0 + 2 * q + 0], h0, l0);
                split_hl(fbuf[r * 64 + c0 + 2 * q + 1], h1, l1);
                hbuf[q] = __halves2half2(h0, h1);
                lbuf[q] = __halves2half2(l0, l1);
            }
            const size_t doff = (size_t)(mrow + r) * NSEQ + n0 + half * 64 + c0;
#pragma unroll
            for (int q = 0; q < 4; ++q) {
                reinterpret_cast<uint4*>(dh + doff)[q] = reinterpret_cast<uint4*>(hbuf)[q];
                reinterpret_cast<uint4*>(dl + doff)[q] = reinterpret_cast<uint4*>(lbuf)[q];
            }
        }
    }
}

__global__ void __launch_bounds__(256) hgemm_qkv()
{
    hgemm_body<true>(g_w_hi, g_w_lo, g_xt_hi, g_xt_lo, nullptr, nullptr,
                     256, (size_t)NSEQ * 256, 0);
}
__global__ void __launch_bounds__(256) hgemm_out(float* __restrict__ out,
                                                 const float* __restrict__ bout)
{
    hgemm_body<false>(g_wout_hi, g_wout_lo, g_outmT_hi, g_outmT_lo, out, bout,
                      512, (size_t)NSEQ * 512, (size_t)256 * NSEQ);
}

// ---------------------------------------------------------------------------
// Kernel D: sim partials via wmma (hi/lo compensated).
// Block = (ks, bh): 64x64 output, contraction over 512 p.
// ---------------------------------------------------------------------------
__global__ void __launch_bounds__(256) sim_kernel()
{
    __shared__ __align__(32) __half sQh[64 * SIMS];
    __shared__ __align__(32) __half sQl[64 * SIMS];
    __shared__ __align__(32) __half sKh[64 * SIMS];
    __shared__ __align__(32) __half sKl[64 * SIMS];

    const int ks = blockIdx.x;
    const int bh = blockIdx.y;
    const int g = bh >> 3, h = bh & 7;
    const int p0 = ks * 512;

    const __half* Qh = g_qk_hi + ((size_t)g * 1024 + h * 64) * NSEQ;
    const __half* Ql = g_qk_lo + ((size_t)g * 1024 + h * 64) * NSEQ;
    const __half* Kh = g_qk_hi + ((size_t)g * 1024 + 512 + h * 64) * NSEQ;
    const __half* Kl = g_qk_lo + ((size_t)g * 1024 + 512 + h * 64) * NSEQ;

    const int tid = threadIdx.x;
    const int wid = tid >> 5;
    const int ti  = wid & 3;       // i tile 0..3
    const int tjg = wid >> 2;      // 0..1 -> j tiles {2*tjg, 2*tjg+1}

    wmma::fragment<wmma::accumulator, 16, 16, 16, float> acc[2];
#pragma unroll
    for (int jj = 0; jj < 2; ++jj) wmma::fill_fragment(acc[jj], 0.0f);

    const int lrow = tid >> 3;    // 0..31 -> two rows per tensor via it
    const int lc8  = tid & 7;

#pragma unroll 1
    for (int pc = 0; pc < 512; pc += 64) {
        __syncthreads();
#pragma unroll
        for (int it = 0; it < 2; ++it) {
            const int row = lrow + it * 32;
            const size_t goff = (size_t)row * NSEQ + p0 + pc + lc8 * 8;
            const int    soff = row * SIMS + lc8 * 8;
            *reinterpret_cast<uint4*>(&sQh[soff]) = *reinterpret_cast<const uint4*>(Qh + goff);
            *reinterpret_cast<uint4*>(&sQl[soff]) = *reinterpret_cast<const uint4*>(Ql + goff);
            *reinterpret_cast<uint4*>(&sKh[soff]) = *reinterpret_cast<const uint4*>(Kh + goff);
            *reinterpret_cast<uint4*>(&sKl[soff]) = *reinterpret_cast<const uint4*>(Kl + goff);
        }
        __syncthreads();

#pragma unroll
        for (int k2 = 0; k2 < 4; ++k2) {
            wmma::fragment<wmma::matrix_a, 16, 16, 16, __half, wmma::row_major> fah, fal;
            wmma::load_matrix_sync(fah, &sQh[(ti * 16) * SIMS + k2 * 16], SIMS);
            wmma::load_matrix_sync(fal, &sQl[(ti * 16) * SIMS + k2 * 16], SIMS);
#pragma unroll
            for (int jj = 0; jj < 2; ++jj) {
                const int tj = tjg * 2 + jj;
                wmma::fragment<wmma::matrix_b, 16, 16, 16, __half, wmma::col_major> fbh, fbl;
                wmma::load_matrix_sync(fbh, &sKh[(tj * 16) * SIMS + k2 * 16], SIMS);
                wmma::load_matrix_sync(fbl, &sKl[(tj * 16) * SIMS + k2 * 16], SIMS);
                wmma::mma_sync(acc[jj], fah, fbh, acc[jj]);
                wmma::mma_sync(acc[jj], fah, fbl, acc[jj]);
                wmma::mma_sync(acc[jj], fal, fbh, acc[jj]);
            }
        }
    }

    float* P = g_part + (((size_t)bh * 32 + ks) * 64) * 64;
#pragma unroll
    for (int jj = 0; jj < 2; ++jj)
        wmma::store_matrix_sync(P + (ti * 16) * 64 + (tjg * 2 + jj) * 16,
                                acc[jj], 64, wmma::mem_row_major);
}

// ---------------------------------------------------------------------------
// Kernel E: reduce + softmax
// ---------------------------------------------------------------------------
__global__ void __launch_bounds__(64) softmax_kernel()
{
    const int i  = blockIdx.x;
    const int bh = blockIdx.y;
    const int j  = threadIdx.x;

    const float* P = g_part + (size_t)bh * 32 * 64 * 64;
    float v = 0.f;
#pragma unroll 8
    for (int ks = 0; ks < 32; ++ks)
        v += P[(size_t)(ks * 64 + i) * 64 + j];
    v *= 0.125f;

    __shared__ float s[64];
    __shared__ float red;
    s[j] = v;
    __syncthreads();
    if (j == 0) {
        float m = s[0];
        for (int t = 1; t < 64; ++t) m = fmaxf(m, s[t]);
        red = m;
    }
    __syncthreads();
    const float e = __expf(v - red);
    s[j] = e;
    __syncthreads();
    if (j == 0) {
        float su = 0.f;
        for (int t = 0; t < 64; ++t) su += s[t];
        red = su;
    }
    __syncthreads();
    g_attn[((size_t)bh * 64 + i) * 64 + j] = e / red;
}

// ---------------------------------------------------------------------------
// Kernel F: outm = attn @ V via wmma (hi/lo), output transposed fp16 hi/lo.
// Block = (p-tile of 128, bh). A = attn 64x64 (smem hi/lo), B = V[j][p]
// staged 16x128 per k-iter, C [64 i][128 p] -> stored col-major -> g_outmT.
// ---------------------------------------------------------------------------
#define OVS 136
__global__ void __launch_bounds__(256) outm_kernel()
{
    __shared__ __align__(32) char sm[32768];
    __half* sAh = reinterpret_cast<__half*>(sm);             // 64 x 72
    __half* sAl = sAh + 64 * SIMS;                           // 64 x 72
    __half* sVh = reinterpret_cast<__half*>(sm + 18432);     // 16 x 136
    __half* sVl = sVh + 16 * OVS;
    float*  fbuf = reinterpret_cast<float*>(sm);             // 128 x 64 (epilogue)

    const int bh = blockIdx.y;
    const int g = bh >> 3, h = bh & 7;
    const int p0 = blockIdx.x * 128;
    const int tid = threadIdx.x;
    const int wid = tid >> 5;
    const int ti  = wid & 3;       // i tile
    const int tjg = wid >> 2;      // p-tile group: tiles tjg*4 .. tjg*4+3

    // stage attn hi/lo
    const float* A = g_attn + (size_t)bh * 4096;
#pragma unroll
    for (int e = 0; e < 16; ++e) {
        const int idx = tid * 16 + e;
        __half hv, lv;
        split_hl(A[idx], hv, lv);
        sAh[(idx >> 6) * SIMS + (idx & 63)] = hv;
        sAl[(idx >> 6) * SIMS + (idx & 63)] = lv;
    }

    const __half* Vh = g_v_hi + ((size_t)g * 512 + h * 64) * NSEQ;
    const __half* Vl = g_v_lo + ((size_t)g * 512 + h * 64) * NSEQ;

    wmma::fragment<wmma::accumulator, 16, 16, 16, float> acc[4];
#pragma unroll
    for (int q = 0; q < 4; ++q) wmma::fill_fragment(acc[q], 0.0f);

#pragma unroll
    for (int jc = 0; jc < 4; ++jc) {
        __syncthreads();
        {   // stage V chunk [16 j][128 p] hi/lo
            const int row = tid >> 4;        // 0..15
            const int c8  = tid & 15;        // 0..15
            const size_t goff = (size_t)(jc * 16 + row) * NSEQ + p0 + c8 * 8;
            const int    soff = row * OVS + c8 * 8;
            *reinterpret_cast<uint4*>(&sVh[soff]) = *reinterpret_cast<const uint4*>(Vh + goff);
            *reinterpret_cast<uint4*>(&sVl[soff]) = *reinterpret_cast<const uint4*>(Vl + goff);
        }
        __syncthreads();

        wmma::fragment<wmma::matrix_a, 16, 16, 16, __half, wmma::row_major> fah, fal;
        wmma::load_matrix_sync(fah, &sAh[(ti * 16) * SIMS + jc * 16], SIMS);
        wmma::load_matrix_sync(fal, &sAl[(ti * 16) * SIMS + jc * 16], SIMS);
#pragma unroll
        for (int q = 0; q < 4; ++q) {
            const int tj = tjg * 4 + q;
            wmma::fragment<wmma::matrix_b, 16, 16, 16, __half, wmma::row_major> fbh, fbl;
            wmma::load_matrix_sync(fbh, &sVh[tj * 16], OVS);
            wmma::load_matrix_sync(fbl, &sVl[tj * 16], OVS);
            wmma::mma_sync(acc[q], fah, fbh, acc[q]);
            wmma::mma_sync(acc[q], fah, fbl, acc[q]);
            wmma::mma_sync(acc[q], fal, fbh, acc[q]);
        }
    }

    // epilogue: col-major store -> [p][i] fp32, then split hi/lo
    __syncthreads();
#pragma unroll
    for (int q = 0; q < 4; ++q) {
        const int tj = tjg * 4 + q;
        wmma::store_matrix_sync(fbuf + (tj * 16) * 64 + ti * 16, acc[q], 64,
                                wmma::mem_col_major);
    }
    __syncthreads();

    const int pl = tid >> 1;          // 0..127
    const int i0 = (tid & 1) * 32;
    __half2 hbuf[16], lbuf[16];
#pragma unroll
    for (int q = 0; q < 16; ++q) {
        __half h0, l0, h1, l1;
        split_hl(fbuf[pl * 64 + i0 + 2 * q + 0], h0, l0);
        split_hl(fbuf[pl * 64 + i0 + 2 * q + 1], h1, l1);
        hbuf[q] = __halves2half2(h0, h1);
        lbuf[q] = __halves2half2(l0, l1);
    }
    const size_t doff = ((size_t)g * NSEQ + p0 + pl) * 512 + h * 64 + i0;
#pragma unroll
    for (int q = 0; q < 4; ++q) {
        reinterpret_cast<uint4*>(g_outmT_hi + doff)[q] = reinterpret_cast<uint4*>(hbuf)[q];
        reinterpret_cast<uint4*>(g_outmT_lo + doff)[q] = reinterpret_cast<uint4*>(lbuf)[q];
    }
}

// ---------------------------------------------------------------------------
extern "C" void kernel_launch(void* const* d_in, const int* in_sizes, int n_in,
                              void* d_out, int out_size)
{
    const float* x    = (const float*)d_in[0];
    const float* Wq   = (const float*)d_in[1];
    const float* Wkv  = (const float*)d_in[2];
    const float* Wout = (const float*)d_in[3];
    const float* bout = (const float*)d_in[4];
    float* out = (float*)d_out;
    (void)in_sizes; (void)n_in; (void)out_size;

    convert_w<<<1536, 256>>>(Wq, Wkv, Wout);
    {
        dim3 grid(NSEQ / 32, 256 / 32, 2);
        convert_x<<<grid, dim3(32, 8)>>>(x);
    }
    {   // QKV = [Wq;Wkv] @ X -> fp16 hi/lo Q/K/V
        dim3 grid(NSEQ / 128, 1536 / 128, 2);
        hgemm_qkv<<<grid, 256>>>();
    }
    sim_kernel<<<dim3(32, 16), 256>>>();
    softmax_kernel<<<dim3(64, 16), 64>>>();
    outm_kernel<<<dim3(NSEQ / 128, 16), 256>>>();
    {   // out = Wout @ OutM + bout
        dim3 grid(NSEQ / 128, 256 / 128, 2);
        hgemm_out<<<grid, 256>>>(out, bout);
    }
}

// round 10
// speedup vs baseline: 3.0465x; 3.0465x over previous
#include <cuda_runtime.h>
#include <cuda_fp16.h>
#include <mma.h>
#include <cstdint>
#include <cstddef>

using namespace nvcuda;

// x: [16][32][128][128] fp32 == X[2][256][16384] (g, f, p)
// Wq: [512][256], Wkv: [1024][256] (K rows 0..511, V rows 512..1023),
// Wout: [256][512], bout: [256], out: [2][256][16384] fp32
//
// Algebraic restructure:
//   G_g = X_g X_g^T                      (gram_kernel + gram_reduce)
//   Sq_g = Wq @ G_g                      (sq_kernel)
//   sim[h] = Sq_g[h] @ Wk[h]^T * 0.125 ; attn = softmax ; U_g[h] = attn @ Wv[h]
//                                        (attn_kernel)
//   W2_g = Wout @ U_g  -> fp16 hi/lo     (w2_kernel)
//   out_g = W2_g @ X_g + bout            (final_kernel)

#define NSEQ 16384
#define SMS2 40    // staging stride, 32-halves rows (+pad)
#define OVS  136   // staging stride, 128-halves rows (+pad)
#define GSP  32    // gram k-splits
#define SAS  36    // attn staging stride in floats (16B-aligned float4 rows)

// ------------------------------ scratch ------------------------------------
__device__ float  g_gpart[(size_t)2 * GSP * 256 * 256];  // gram partials
__device__ float  g_gram [(size_t)2 * 256 * 256];
__device__ float  g_sq   [(size_t)2 * 512 * 256];
__device__ float  g_u    [(size_t)2 * 512 * 256];
__device__ __half g_w2_h [(size_t)2 * 256 * 256];
__device__ __half g_w2_l [(size_t)2 * 256 * 256];

__device__ __forceinline__ void split_hl(float v, __half& hi, __half& lo) {
    hi = __float2half_rn(v);
    lo = __float2half_rn(v - __half2float(hi));
}

// ---------------------------------------------------------------------------
// Kernel 1: gram partials. G_part[g][ks] = Xg[:, ks-slice] Xg[:, ks-slice]^T.
// Block: 128x128 tile of G, contraction over 512 p. hi/lo 3-term wmma,
// split from fp32 during staging. 8 warps 2(m) x 4(n).
// ---------------------------------------------------------------------------
__global__ void __launch_bounds__(256) gram_kernel(const float* __restrict__ x)
{
    __shared__ __align__(32) __half sAh[128 * SMS2];
    __shared__ __align__(32) __half sAl[128 * SMS2];
    __shared__ __align__(32) __half sBh[128 * SMS2];
    __shared__ __align__(32) __half sBl[128 * SMS2];

    const int ks = blockIdx.x;                    // 0..31
    const int tm = blockIdx.y >> 1, tn = blockIdx.y & 1;
    const int g  = blockIdx.z;
    const float* Xg = x + (size_t)g * 256 * NSEQ;
    const int p0 = ks * 512;

    const int tid = threadIdx.x;
    const int wid = tid >> 5;
    const int wm = wid >> 2, wn = wid & 3;

    wmma::fragment<wmma::accumulator, 16, 16, 16, float> acc[4][2];
#pragma unroll
    for (int mi = 0; mi < 4; ++mi)
#pragma unroll
        for (int ni = 0; ni < 2; ++ni) wmma::fill_fragment(acc[mi][ni], 0.0f);

#pragma unroll 1
    for (int pc = 0; pc < 512; pc += 32) {
        __syncthreads();
#pragma unroll
        for (int it = 0; it < 4; ++it) {
            const int idx = tid + it * 256;       // 0..1023
            const int row = idx >> 3, c4 = idx & 7;
            const float4 va = *reinterpret_cast<const float4*>(
                Xg + (size_t)(tm * 128 + row) * NSEQ + p0 + pc + c4 * 4);
            const float4 vb = *reinterpret_cast<const float4*>(
                Xg + (size_t)(tn * 128 + row) * NSEQ + p0 + pc + c4 * 4);
            const int so = row * SMS2 + c4 * 4;
            __half h0, l0, h1, l1, h2, l2, h3, l3;
            split_hl(va.x, h0, l0); split_hl(va.y, h1, l1);
            split_hl(va.z, h2, l2); split_hl(va.w, h3, l3);
            *reinterpret_cast<__half2*>(&sAh[so])     = __halves2half2(h0, h1);
            *reinterpret_cast<__half2*>(&sAh[so + 2]) = __halves2half2(h2, h3);
            *reinterpret_cast<__half2*>(&sAl[so])     = __halves2half2(l0, l1);
            *reinterpret_cast<__half2*>(&sAl[so + 2]) = __halves2half2(l2, l3);
            split_hl(vb.x, h0, l0); split_hl(vb.y, h1, l1);
            split_hl(vb.z, h2, l2); split_hl(vb.w, h3, l3);
            *reinterpret_cast<__half2*>(&sBh[so])     = __halves2half2(h0, h1);
            *reinterpret_cast<__half2*>(&sBh[so + 2]) = __halves2half2(h2, h3);
            *reinterpret_cast<__half2*>(&sBl[so])     = __halves2half2(l0, l1);
            *reinterpret_cast<__half2*>(&sBl[so + 2]) = __halves2half2(l2, l3);
        }
        __syncthreads();

#pragma unroll
        for (int k2 = 0; k2 < 2; ++k2) {
            wmma::fragment<wmma::matrix_a, 16, 16, 16, __half, wmma::row_major> fah[4], fal[4];
            wmma::fragment<wmma::matrix_b, 16, 16, 16, __half, wmma::col_major> fbh[2], fbl[2];
#pragma unroll
            for (int mi = 0; mi < 4; ++mi) {
                const int ro = (wm * 64 + mi * 16) * SMS2 + k2 * 16;
                wmma::load_matrix_sync(fah[mi], &sAh[ro], SMS2);
                wmma::load_matrix_sync(fal[mi], &sAl[ro], SMS2);
            }
#pragma unroll
            for (int ni = 0; ni < 2; ++ni) {
                const int ro = (wn * 32 + ni * 16) * SMS2 + k2 * 16;
                wmma::load_matrix_sync(fbh[ni], &sBh[ro], SMS2);
                wmma::load_matrix_sync(fbl[ni], &sBl[ro], SMS2);
            }
#pragma unroll
            for (int mi = 0; mi < 4; ++mi)
#pragma unroll
                for (int ni = 0; ni < 2; ++ni) {
                    wmma::mma_sync(acc[mi][ni], fah[mi], fbh[ni], acc[mi][ni]);
                    wmma::mma_sync(acc[mi][ni], fah[mi], fbl[ni], acc[mi][ni]);
                    wmma::mma_sync(acc[mi][ni], fal[mi], fbh[ni], acc[mi][ni]);
                }
        }
    }

    float* P = g_gpart + (size_t)(g * GSP + ks) * 65536;
#pragma unroll
    for (int mi = 0; mi < 4; ++mi)
#pragma unroll
        for (int ni = 0; ni < 2; ++ni)
            wmma::store_matrix_sync(
                P + (size_t)(tm * 128 + wm * 64 + mi * 16) * 256
                  + tn * 128 + wn * 32 + ni * 16,
                acc[mi][ni], 256, wmma::mem_row_major);
}

// ---------------------------------------------------------------------------
// Kernel 2: reduce gram partials.
// ---------------------------------------------------------------------------
__global__ void __launch_bounds__(256) gram_reduce()
{
    const int a = blockIdx.x, g = blockIdx.y, b = threadIdx.x;
    float s = 0.f;
#pragma unroll 8
    for (int ks = 0; ks < GSP; ++ks)
        s += g_gpart[((size_t)(g * GSP + ks) * 256 + a) * 256 + b];
    g_gram[((size_t)g * 256 + a) * 256 + b] = s;
}

// ---------------------------------------------------------------------------
// Kernel 3: Sq_g = Wq @ G_g   (512x256 per group, K=256, fp32)
// ---------------------------------------------------------------------------
__global__ void __launch_bounds__(256) sq_kernel(const float* __restrict__ Wq)
{
    const int m = blockIdx.x, g = blockIdx.y, n = threadIdx.x;
    const float* G = g_gram + (size_t)g * 65536;
    const float* wr = Wq + (size_t)m * 256;
    float s = 0.f;
#pragma unroll 8
    for (int k = 0; k < 256; ++k)
        s += wr[k] * G[k * 256 + n];
    g_sq[((size_t)g * 512 + m) * 256 + n] = s;
}

// ---------------------------------------------------------------------------
// Kernel 4: per (g,h): sim = Sq[h] Wk[h]^T * 0.125 ; softmax ; U = attn Wv[h].
// All fp32, in-block. Staging stride SAS=36 floats (16B-aligned rows).
// ---------------------------------------------------------------------------
__global__ void __launch_bounds__(256) attn_kernel(const float* __restrict__ Wkv)
{
    __shared__ __align__(16) char smbuf[16384 + 2 * 64 * SAS * 4];
    float* s_sim = reinterpret_cast<float*>(smbuf);              // [64][64]
    float* s_a   = reinterpret_cast<float*>(smbuf + 16384);      // [64][SAS]
    float* s_b   = s_a + 64 * SAS;                               // [64][SAS]
    float* s_w   = s_a;                                          // [64][64] alias

    const int h = blockIdx.x, g = blockIdx.y;
    const int tid = threadIdx.x;

    const float* SQ = g_sq + ((size_t)g * 512 + h * 64) * 256;
    const float* WK = Wkv + (size_t)(h * 64) * 256;

    float accv[16];
#pragma unroll
    for (int q = 0; q < 16; ++q) accv[q] = 0.f;

#pragma unroll 1
    for (int kc = 0; kc < 256; kc += 32) {
        __syncthreads();
#pragma unroll
        for (int it = 0; it < 2; ++it) {
            const int idx = tid + it * 256;      // 0..511
            const int row = idx >> 3, c4 = idx & 7;
            const float4 va = *reinterpret_cast<const float4*>(SQ + (size_t)row * 256 + kc + c4 * 4);
            const float4 vb = *reinterpret_cast<const float4*>(WK + (size_t)row * 256 + kc + c4 * 4);
            *reinterpret_cast<float4*>(&s_a[row * SAS + c4 * 4]) = va;
            *reinterpret_cast<float4*>(&s_b[row * SAS + c4 * 4]) = vb;
        }
        __syncthreads();
#pragma unroll
        for (int q = 0; q < 16; ++q) {
            const int idx = q * 256 + tid;
            const int i = idx >> 6, j = idx & 63;
            float s = 0.f;
#pragma unroll
            for (int k = 0; k < 32; ++k)
                s += s_a[i * SAS + k] * s_b[j * SAS + k];
            accv[q] += s;
        }
    }
    __syncthreads();
#pragma unroll
    for (int q = 0; q < 16; ++q)
        s_sim[q * 256 + tid] = accv[q] * 0.125f;
    __syncthreads();

    // softmax over j, one thread per row
    if (tid < 64) {
        float m = -1e30f;
#pragma unroll 8
        for (int j = 0; j < 64; ++j) m = fmaxf(m, s_sim[tid * 64 + j]);
        float su = 0.f;
#pragma unroll 8
        for (int j = 0; j < 64; ++j) {
            const float e = __expf(s_sim[tid * 64 + j] - m);
            s_sim[tid * 64 + j] = e;
            su += e;
        }
        const float inv = 1.f / su;
#pragma unroll 8
        for (int j = 0; j < 64; ++j) s_sim[tid * 64 + j] *= inv;
    }

    // U = attn @ Wv[h], f chunked by 64 through smem
    const float* WV = Wkv + (size_t)(512 + h * 64) * 256;
    float* U = g_u + ((size_t)g * 512 + h * 64) * 256;
#pragma unroll 1
    for (int fc = 0; fc < 256; fc += 64) {
        __syncthreads();
#pragma unroll
        for (int it = 0; it < 4; ++it) {
            const int idx = tid + it * 256;      // 0..1023
            const int row = idx >> 4, c4 = idx & 15;
            *reinterpret_cast<float4*>(&s_w[row * 64 + c4 * 4]) =
                *reinterpret_cast<const float4*>(WV + (size_t)row * 256 + fc + c4 * 4);
        }
        __syncthreads();
#pragma unroll
        for (int q = 0; q < 16; ++q) {
            const int idx = q * 256 + tid;
            const int i = idx >> 6, fo = idx & 63;
            float s = 0.f;
#pragma unroll
            for (int j = 0; j < 64; ++j)
                s += s_sim[i * 64 + j] * s_w[j * 64 + fo];
            U[(size_t)i * 256 + fc + fo] = s;
        }
    }
}

// ---------------------------------------------------------------------------
// Kernel 5: W2_g = Wout @ U_g  -> fp16 hi/lo  (256x256 per group, K=512)
// ---------------------------------------------------------------------------
__global__ void __launch_bounds__(256) w2_kernel(const float* __restrict__ Wout)
{
    const int m = blockIdx.x, g = blockIdx.y, n = threadIdx.x;
    const float* wr = Wout + (size_t)m * 512;
    const float* Ug = g_u + (size_t)g * 512 * 256;
    float s = 0.f;
#pragma unroll 8
    for (int c = 0; c < 512; ++c)
        s += wr[c] * Ug[(size_t)c * 256 + n];
    __half hv, lv;
    split_hl(s, hv, lv);
    g_w2_h[((size_t)g * 256 + m) * 256 + n] = hv;
    g_w2_l[((size_t)g * 256 + m) * 256 + n] = lv;
}

// ---------------------------------------------------------------------------
// Kernel 6: out_g = W2_g @ X_g + bout.  M=256, N=16384, K=256.
// A = W2 hi/lo fp16 K-major; B = X fp32 [k][p] split hi/lo in staging
// (matrix_b ROW-major). Tile 128x128, K-chunk 32, 8 warps 2x4.
// ---------------------------------------------------------------------------
__global__ void __launch_bounds__(256) final_kernel(const float* __restrict__ x,
                                                    const float* __restrict__ bout,
                                                    float* __restrict__ out)
{
    __shared__ __align__(32) __half sAh[128 * SMS2];
    __shared__ __align__(32) __half sAl[128 * SMS2];
    __shared__ __align__(32) __half sBh[32 * OVS];
    __shared__ __align__(32) __half sBl[32 * OVS];
    __shared__ __align__(32) float  brep[128 * 16];

    const int tid = threadIdx.x;
    const int wid = tid >> 5;
    const int wm = wid >> 2, wn = wid & 3;
    const int p0 = blockIdx.x * 128;
    const int m0 = blockIdx.y * 128;
    const int g  = blockIdx.z;

    const __half* Ah = g_w2_h + (size_t)g * 65536;
    const __half* Al = g_w2_l + (size_t)g * 65536;
    const float*  Xg = x + (size_t)g * 256 * NSEQ;

    for (int r = tid; r < 128; r += 256) {
        const float bv = bout[m0 + r];
#pragma unroll
        for (int c = 0; c < 16; ++c) brep[r * 16 + c] = bv;
    }
    __syncthreads();

    wmma::fragment<wmma::accumulator, 16, 16, 16, float> acc[4][2];
#pragma unroll
    for (int mi = 0; mi < 4; ++mi)
#pragma unroll
        for (int ni = 0; ni < 2; ++ni)
            wmma::load_matrix_sync(acc[mi][ni],
                                   &brep[(wm * 64 + mi * 16) * 16], 16,
                                   wmma::mem_row_major);

#pragma unroll 1
    for (int kk = 0; kk < 256; kk += 32) {
        __syncthreads();
        // stage A (fp16 hi/lo): 128 rows x 32 halves
#pragma unroll
        for (int it = 0; it < 2; ++it) {
            const int idx = tid + it * 256;      // 0..511
            const int row = idx >> 2, c4 = idx & 3;
            const size_t go = (size_t)(m0 + row) * 256 + kk + c4 * 8;
            const int    so = row * SMS2 + c4 * 8;
            *reinterpret_cast<uint4*>(&sAh[so]) = *reinterpret_cast<const uint4*>(Ah + go);
            *reinterpret_cast<uint4*>(&sAl[so]) = *reinterpret_cast<const uint4*>(Al + go);
        }
        // stage B (fp32 -> hi/lo): 32 k-rows x 128 p
#pragma unroll
        for (int it = 0; it < 4; ++it) {
            const int idx = tid + it * 256;      // 0..1023
            const int row = idx >> 5, c4 = idx & 31;
            const float4 v = *reinterpret_cast<const float4*>(
                Xg + (size_t)(kk + row) * NSEQ + p0 + c4 * 4);
            const int so = row * OVS + c4 * 4;
            __half h0, l0, h1, l1, h2, l2, h3, l3;
            split_hl(v.x, h0, l0); split_hl(v.y, h1, l1);
            split_hl(v.z, h2, l2); split_hl(v.w, h3, l3);
            *reinterpret_cast<__half2*>(&sBh[so])     = __halves2half2(h0, h1);
            *reinterpret_cast<__half2*>(&sBh[so + 2]) = __halves2half2(h2, h3);
            *reinterpret_cast<__half2*>(&sBl[so])     = __halves2half2(l0, l1);
            *reinterpret_cast<__half2*>(&sBl[so + 2]) = __halves2half2(l2, l3);
        }
        __syncthreads();

#pragma unroll
        for (int k2 = 0; k2 < 2; ++k2) {
            wmma::fragment<wmma::matrix_a, 16, 16, 16, __half, wmma::row_major> fah[4], fal[4];
            wmma::fragment<wmma::matrix_b, 16, 16, 16, __half, wmma::row_major> fbh[2], fbl[2];
#pragma unroll
            for (int mi = 0; mi < 4; ++mi) {
                const int ro = (wm * 64 + mi * 16) * SMS2 + k2 * 16;
                wmma::load_matrix_sync(fah[mi], &sAh[ro], SMS2);
                wmma::load_matrix_sync(fal[mi], &sAl[ro], SMS2);
            }
#pragma unroll
            for (int ni = 0; ni < 2; ++ni) {
                const int co = (k2 * 16) * OVS + wn * 32 + ni * 16;
                wmma::load_matrix_sync(fbh[ni], &sBh[co], OVS);
                wmma::load_matrix_sync(fbl[ni], &sBl[co], OVS);
            }
#pragma unroll
            for (int mi = 0; mi < 4; ++mi)
#pragma unroll
                for (int ni = 0; ni < 2; ++ni) {
                    wmma::mma_sync(acc[mi][ni], fah[mi], fbh[ni], acc[mi][ni]);
                    wmma::mma_sync(acc[mi][ni], fah[mi], fbl[ni], acc[mi][ni]);
                    wmma::mma_sync(acc[mi][ni], fal[mi], fbh[ni], acc[mi][ni]);
                }
        }
    }

    float* C = out + (size_t)g * 256 * NSEQ;
#pragma unroll
    for (int mi = 0; mi < 4; ++mi)
#pragma unroll
        for (int ni = 0; ni < 2; ++ni)
            wmma::store_matrix_sync(
                C + (size_t)(m0 + wm * 64 + mi * 16) * NSEQ + p0 + wn * 32 + ni * 16,
                acc[mi][ni], NSEQ, wmma::mem_row_major);
}

// ---------------------------------------------------------------------------
extern "C" void kernel_launch(void* const* d_in, const int* in_sizes, int n_in,
                              void* d_out, int out_size)
{
    const float* x    = (const float*)d_in[0];
    const float* Wq   = (const float*)d_in[1];
    const float* Wkv  = (const float*)d_in[2];
    const float* Wout = (const float*)d_in[3];
    const float* bout = (const float*)d_in[4];
    float* out = (float*)d_out;
    (void)in_sizes; (void)n_in; (void)out_size;

    gram_kernel <<<dim3(GSP, 4, 2), 256>>>(x);
    gram_reduce <<<dim3(256, 2), 256>>>();
    sq_kernel   <<<dim3(512, 2), 256>>>(Wq);
    attn_kernel <<<dim3(8, 2), 256>>>(Wkv);
    w2_kernel   <<<dim3(256, 2), 256>>>(Wout);
    final_kernel<<<dim3(NSEQ / 128, 2, 2), 256>>>(x, bout, out);
}

// round 11
// speedup vs baseline: 3.1999x; 1.0504x over previous
#include <cuda_runtime.h>
#include <cuda_fp16.h>
#include <mma.h>
#include <cstdint>
#include <cstddef>

using namespace nvcuda;

// x: [16][32][128][128] fp32 == X[2][256][16384] (g, f, p)
// Wq: [512][256], Wkv: [1024][256] (K rows 0..511, V rows 512..1023),
// Wout: [256][512], bout: [256], out: [2][256][16384] fp32
//
//   Xh/Xl = split(X)                     (convert_x)
//   G_g = X_g X_g^T  (symmetric)         (gram_kernel + gram_reduce)
//   Sq_g = Wq @ G_g                      (sq_kernel)
//   simp = Sq[h] @ Wk[h]^T (k-split)     (simp_kernel)
//   attn = softmax(0.125 * sum simp)     (softmax_kernel)
//   U_g[h] = attn @ Wv[h]                (u_kernel)
//   W2_g = Wout @ U_g -> fp16 hi/lo      (w2_kernel)
//   out_g = W2_g @ X_g + bout            (final_kernel)

#define NSEQ 16384
#define SMS2 40    // fp16 staging stride, 32-half rows (+pad)
#define OVS  136   // fp16 staging stride, 128-half rows (+pad)
#define GSP  64    // gram k-splits
#define FAS  68    // fp32 staging stride (floats), 64-wide tiles

// ------------------------------ scratch ------------------------------------
__device__ __half g_xh  [(size_t)2 * 256 * 16384];      // X hi
__device__ __half g_xl  [(size_t)2 * 256 * 16384];      // X lo
__device__ float  g_gpart[(size_t)2 * GSP * 256 * 256]; // gram partials
__device__ float  g_gram [(size_t)2 * 256 * 256];
__device__ float  g_sq   [(size_t)2 * 512 * 256];
__device__ float  g_simp [(size_t)16 * 4 * 64 * 64];    // sim k-split partials
__device__ float  g_attn [(size_t)16 * 64 * 64];
__device__ float  g_u    [(size_t)2 * 512 * 256];
__device__ __half g_w2_h [(size_t)2 * 256 * 256];
__device__ __half g_w2_l [(size_t)2 * 256 * 256];

__device__ __forceinline__ void split_hl(float v, __half& hi, __half& lo) {
    hi = __float2half_rn(v);
    lo = __float2half_rn(v - __half2float(hi));
}

// ---------------------------------------------------------------------------
// Kernel 0: X fp32 -> Xh/Xl fp16 (same [g][f][p] layout)
// ---------------------------------------------------------------------------
__global__ void __launch_bounds__(256) convert_x(const float* __restrict__ x)
{
    const size_t base = ((size_t)blockIdx.y * 256 + blockIdx.x) * NSEQ;
    const float4* src = reinterpret_cast<const float4*>(x + base);
    uint4* dh = reinterpret_cast<uint4*>(g_xh + base);
    uint4* dl = reinterpret_cast<uint4*>(g_xl + base);
    for (int t = threadIdx.x; t < 2048; t += 256) {
        const float4 v0 = src[2 * t], v1 = src[2 * t + 1];
        __half h[8], l[8];
        split_hl(v0.x, h[0], l[0]); split_hl(v0.y, h[1], l[1]);
        split_hl(v0.z, h[2], l[2]); split_hl(v0.w, h[3], l[3]);
        split_hl(v1.x, h[4], l[4]); split_hl(v1.y, h[5], l[5]);
        split_hl(v1.z, h[6], l[6]); split_hl(v1.w, h[7], l[7]);
        dh[t] = *reinterpret_cast<uint4*>(h);
        dl[t] = *reinterpret_cast<uint4*>(l);
    }
}

// ---------------------------------------------------------------------------
// Kernel 1: gram partials (symmetric). blockIdx.y: 0->(0,0), 1->(1,0), 2->(1,1).
// 128x128 tile, contraction over 256 p per k-split, hi/lo 3-term wmma.
// ---------------------------------------------------------------------------
__global__ void __launch_bounds__(256) gram_kernel()
{
    __shared__ __align__(32) __half sAh[128 * SMS2];
    __shared__ __align__(32) __half sAl[128 * SMS2];
    __shared__ __align__(32) __half sBh[128 * SMS2];
    __shared__ __align__(32) __half sBl[128 * SMS2];

    const int ks = blockIdx.x;                    // 0..GSP-1
    const int y  = blockIdx.y;                    // 0..2
    const int g  = blockIdx.z;
    const int tm = (y >= 1), tn = (y == 2);
    const bool diag = (tm == tn);
    const int p0 = ks * 256;

    const __half* Xh = g_xh + (size_t)g * 256 * NSEQ;
    const __half* Xl = g_xl + (size_t)g * 256 * NSEQ;

    const int tid = threadIdx.x;
    const int wid = tid >> 5;
    const int wm = wid >> 2, wn = wid & 3;

    wmma::fragment<wmma::accumulator, 16, 16, 16, float> acc[4][2];
#pragma unroll
    for (int mi = 0; mi < 4; ++mi)
#pragma unroll
        for (int ni = 0; ni < 2; ++ni) wmma::fill_fragment(acc[mi][ni], 0.0f);

    const __half* pBh = diag ? sAh : sBh;
    const __half* pBl = diag ? sAl : sBl;

#pragma unroll 1
    for (int pc = 0; pc < 256; pc += 32) {
        __syncthreads();
#pragma unroll
        for (int it = 0; it < 2; ++it) {
            const int idx = tid + it * 256;       // 0..511
            const int row = idx >> 2, c4 = idx & 3;
            const size_t ga = (size_t)(tm * 128 + row) * NSEQ + p0 + pc + c4 * 8;
            const int    so = row * SMS2 + c4 * 8;
            *reinterpret_cast<uint4*>(&sAh[so]) = *reinterpret_cast<const uint4*>(Xh + ga);
            *reinterpret_cast<uint4*>(&sAl[so]) = *reinterpret_cast<const uint4*>(Xl + ga);
            if (!diag) {
                const size_t gb = (size_t)(tn * 128 + row) * NSEQ + p0 + pc + c4 * 8;
                *reinterpret_cast<uint4*>(&sBh[so]) = *reinterpret_cast<const uint4*>(Xh + gb);
                *reinterpret_cast<uint4*>(&sBl[so]) = *reinterpret_cast<const uint4*>(Xl + gb);
            }
        }
        __syncthreads();

#pragma unroll
        for (int k2 = 0; k2 < 2; ++k2) {
            wmma::fragment<wmma::matrix_a, 16, 16, 16, __half, wmma::row_major> fah[4], fal[4];
            wmma::fragment<wmma::matrix_b, 16, 16, 16, __half, wmma::col_major> fbh[2], fbl[2];
#pragma unroll
            for (int mi = 0; mi < 4; ++mi) {
                const int ro = (wm * 64 + mi * 16) * SMS2 + k2 * 16;
                wmma::load_matrix_sync(fah[mi], &sAh[ro], SMS2);
                wmma::load_matrix_sync(fal[mi], &sAl[ro], SMS2);
            }
#pragma unroll
            for (int ni = 0; ni < 2; ++ni) {
                const int ro = (wn * 32 + ni * 16) * SMS2 + k2 * 16;
                wmma::load_matrix_sync(fbh[ni], &pBh[ro], SMS2);
                wmma::load_matrix_sync(fbl[ni], &pBl[ro], SMS2);
            }
#pragma unroll
            for (int mi = 0; mi < 4; ++mi)
#pragma unroll
                for (int ni = 0; ni < 2; ++ni) {
                    wmma::mma_sync(acc[mi][ni], fah[mi], fbh[ni], acc[mi][ni]);
                    wmma::mma_sync(acc[mi][ni], fah[mi], fbl[ni], acc[mi][ni]);
                    wmma::mma_sync(acc[mi][ni], fal[mi], fbh[ni], acc[mi][ni]);
                }
        }
    }

    float* P = g_gpart + (size_t)(g * GSP + ks) * 65536;
#pragma unroll
    for (int mi = 0; mi < 4; ++mi)
#pragma unroll
        for (int ni = 0; ni < 2; ++ni) {
            const int rb = tm * 128 + wm * 64 + mi * 16;
            const int cb = tn * 128 + wn * 32 + ni * 16;
            wmma::store_matrix_sync(P + (size_t)rb * 256 + cb, acc[mi][ni],
                                    256, wmma::mem_row_major);
            if (tm != tn)   // mirror into upper-right block (transpose)
                wmma::store_matrix_sync(P + (size_t)cb * 256 + rb, acc[mi][ni],
                                        256, wmma::mem_col_major);
        }
}

// ---------------------------------------------------------------------------
// Kernel 2: reduce gram partials.
// ---------------------------------------------------------------------------
__global__ void __launch_bounds__(256) gram_reduce()
{
    const int a = blockIdx.x, g = blockIdx.y, b = threadIdx.x;
    float s = 0.f;
#pragma unroll 8
    for (int ks = 0; ks < GSP; ++ks)
        s += g_gpart[((size_t)(g * GSP + ks) * 256 + a) * 256 + b];
    g_gram[((size_t)g * 256 + a) * 256 + b] = s;
}

// ---------------------------------------------------------------------------
// Kernel 3: Sq_g = Wq @ G_g   (512x256 per group, K=256, fp32)
// ---------------------------------------------------------------------------
__global__ void __launch_bounds__(256) sq_kernel(const float* __restrict__ Wq)
{
    const int m = blockIdx.x, g = blockIdx.y, n = threadIdx.x;
    const float* G = g_gram + (size_t)g * 65536;
    const float* wr = Wq + (size_t)m * 256;
    float s0 = 0.f, s1 = 0.f, s2 = 0.f, s3 = 0.f;
#pragma unroll 4
    for (int k = 0; k < 256; k += 4) {
        s0 += wr[k + 0] * G[(k + 0) * 256 + n];
        s1 += wr[k + 1] * G[(k + 1) * 256 + n];
        s2 += wr[k + 2] * G[(k + 2) * 256 + n];
        s3 += wr[k + 3] * G[(k + 3) * 256 + n];
    }
    g_sq[((size_t)g * 512 + m) * 256 + n] = (s0 + s1) + (s2 + s3);
}

// ---------------------------------------------------------------------------
// Kernel 4: sim partials. grid (4 ksplit, 16 gh). 64x64 out, K=64 per block.
// 16x16 threads, 4x4 micro-tile, fp32.
// ---------------------------------------------------------------------------
__global__ void __launch_bounds__(256) simp_kernel(const float* __restrict__ Wkv)
{
    __shared__ __align__(16) float s_q[64 * FAS];
    __shared__ __align__(16) float s_k[64 * FAS];

    const int ks = blockIdx.x, gh = blockIdx.y;
    const int g = gh >> 3, h = gh & 7;
    const int tid = threadIdx.x;

    const float* SQ = g_sq + ((size_t)g * 512 + h * 64) * 256 + ks * 64;
    const float* WK = Wkv + (size_t)(h * 64) * 256 + ks * 64;

#pragma unroll
    for (int it = 0; it < 4; ++it) {
        const int idx = tid + it * 256;          // 0..1023
        const int row = idx >> 4, c4 = idx & 15;
        *reinterpret_cast<float4*>(&s_q[row * FAS + c4 * 4]) =
            *reinterpret_cast<const float4*>(SQ + (size_t)row * 256 + c4 * 4);
        *reinterpret_cast<float4*>(&s_k[row * FAS + c4 * 4]) =
            *reinterpret_cast<const float4*>(WK + (size_t)row * 256 + c4 * 4);
    }
    __syncthreads();

    const int i0 = (tid >> 4) * 4, j0 = (tid & 15) * 4;
    float acc[4][4] = {};
#pragma unroll
    for (int k = 0; k < 64; k += 4) {
        float4 qv[4], kv[4];
#pragma unroll
        for (int a = 0; a < 4; ++a) {
            qv[a] = *reinterpret_cast<const float4*>(&s_q[(i0 + a) * FAS + k]);
            kv[a] = *reinterpret_cast<const float4*>(&s_k[(j0 + a) * FAS + k]);
        }
#pragma unroll
        for (int a = 0; a < 4; ++a)
#pragma unroll
            for (int b = 0; b < 4; ++b)
                acc[a][b] += qv[a].x * kv[b].x + qv[a].y * kv[b].y
                           + qv[a].z * kv[b].z + qv[a].w * kv[b].w;
    }

    float* P = g_simp + (size_t)(gh * 4 + ks) * 4096;
#pragma unroll
    for (int a = 0; a < 4; ++a)
        *reinterpret_cast<float4*>(&P[(i0 + a) * 64 + j0]) =
            make_float4(acc[a][0], acc[a][1], acc[a][2], acc[a][3]);
}

// ---------------------------------------------------------------------------
// Kernel 5: reduce sim partials + scale + softmax. grid (64, 16), 64 thr.
// ---------------------------------------------------------------------------
__global__ void __launch_bounds__(64) softmax_kernel()
{
    const int i  = blockIdx.x;
    const int gh = blockIdx.y;
    const int j  = threadIdx.x;

    float v = 0.f;
#pragma unroll
    for (int ks = 0; ks < 4; ++ks)
        v += g_simp[(size_t)(gh * 4 + ks) * 4096 + i * 64 + j];
    v *= 0.125f;

    __shared__ float s[64];
    __shared__ float red;
    s[j] = v;
    __syncthreads();
    if (j == 0) {
        float m = s[0];
        for (int t = 1; t < 64; ++t) m = fmaxf(m, s[t]);
        red = m;
    }
    __syncthreads();
    const float e = __expf(v - red);
    s[j] = e;
    __syncthreads();
    if (j == 0) {
        float su = 0.f;
        for (int t = 0; t < 64; ++t) su += s[t];
        red = su;
    }
    __syncthreads();
    g_attn[(size_t)gh * 4096 + i * 64 + j] = e / red;
}

// ---------------------------------------------------------------------------
// Kernel 6: U = attn @ Wv. grid (4 ftile, 16 gh). 64x64 out, K=64.
// ---------------------------------------------------------------------------
__global__ void __launch_bounds__(256) u_kernel(const float* __restrict__ Wkv)
{
    __shared__ __align__(16) float s_a[64 * FAS];
    __shared__ __align__(16) float s_w[64 * FAS];

    const int ft = blockIdx.x, gh = blockIdx.y;
    const int g = gh >> 3, h = gh & 7;
    const int tid = threadIdx.x;

    const float* A  = g_attn + (size_t)gh * 4096;
    const float* WV = Wkv + (size_t)(512 + h * 64) * 256 + ft * 64;

    // stage attn (64x64) and Wv tile (64 j x 64 f)
#pragma unroll
    for (int it = 0; it < 4; ++it) {
        const int idx = tid + it * 256;
        const int row = idx >> 4, c4 = idx & 15;
        *reinterpret_cast<float4*>(&s_a[row * FAS + c4 * 4]) =
            *reinterpret_cast<const float4*>(A + (size_t)row * 64 + c4 * 4);
        *reinterpret_cast<float4*>(&s_w[row * FAS + c4 * 4]) =
            *reinterpret_cast<const float4*>(WV + (size_t)row * 256 + c4 * 4);
    }
    __syncthreads();

    const int i0 = (tid >> 4) * 4, f0 = (tid & 15) * 4;
    float acc[4][4] = {};
#pragma unroll
    for (int j = 0; j < 64; ++j) {
        const float4 wv = *reinterpret_cast<const float4*>(&s_w[j * FAS + f0]);
        float av[4];
#pragma unroll
        for (int a = 0; a < 4; ++a) av[a] = s_a[(i0 + a) * FAS + j];
#pragma unroll
        for (int a = 0; a < 4; ++a) {
            acc[a][0] += av[a] * wv.x; acc[a][1] += av[a] * wv.y;
            acc[a][2] += av[a] * wv.z; acc[a][3] += av[a] * wv.w;
        }
    }

    float* U = g_u + ((size_t)g * 512 + h * 64) * 256 + ft * 64;
#pragma unroll
    for (int a = 0; a < 4; ++a)
        *reinterpret_cast<float4*>(&U[(size_t)(i0 + a) * 256 + f0]) =
            make_float4(acc[a][0], acc[a][1], acc[a][2], acc[a][3]);
}

// ---------------------------------------------------------------------------
// Kernel 7: W2_g = Wout @ U_g -> fp16 hi/lo (256x256 per group, K=512)
// ---------------------------------------------------------------------------
__global__ void __launch_bounds__(256) w2_kernel(const float* __restrict__ Wout)
{
    const int m = blockIdx.x, g = blockIdx.y, n = threadIdx.x;
    const float* wr = Wout + (size_t)m * 512;
    const float* Ug = g_u + (size_t)g * 512 * 256;
    float s0 = 0.f, s1 = 0.f, s2 = 0.f, s3 = 0.f;
#pragma unroll 4
    for (int c = 0; c < 512; c += 4) {
        s0 += wr[c + 0] * Ug[(size_t)(c + 0) * 256 + n];
        s1 += wr[c + 1] * Ug[(size_t)(c + 1) * 256 + n];
        s2 += wr[c + 2] * Ug[(size_t)(c + 2) * 256 + n];
        s3 += wr[c + 3] * Ug[(size_t)(c + 3) * 256 + n];
    }
    __half hv, lv;
    split_hl((s0 + s1) + (s2 + s3), hv, lv);
    g_w2_h[((size_t)g * 256 + m) * 256 + n] = hv;
    g_w2_l[((size_t)g * 256 + m) * 256 + n] = lv;
}

// ---------------------------------------------------------------------------
// Kernel 8: out_g = W2_g @ X_g + bout.  M=256, N=16384, K=256.
// A = W2 hi/lo K-major; B = Xh/Xl [k][p] row-major. Tile 128x128, K-chunk 32.
// ---------------------------------------------------------------------------
__global__ void __launch_bounds__(256) final_kernel(const float* __restrict__ bout,
                                                    float* __restrict__ out)
{
    __shared__ __align__(32) __half sAh[128 * SMS2];
    __shared__ __align__(32) __half sAl[128 * SMS2];
    __shared__ __align__(32) __half sBh[32 * OVS];
    __shared__ __align__(32) __half sBl[32 * OVS];
    __shared__ __align__(32) float  brep[128 * 16];

    const int tid = threadIdx.x;
    const int wid = tid >> 5;
    const int wm = wid >> 2, wn = wid & 3;
    const int p0 = blockIdx.x * 128;
    const int m0 = blockIdx.y * 128;
    const int g  = blockIdx.z;

    const __half* Ah = g_w2_h + (size_t)g * 65536;
    const __half* Al = g_w2_l + (size_t)g * 65536;
    const __half* Xh = g_xh + (size_t)g * 256 * NSEQ;
    const __half* Xl = g_xl + (size_t)g * 256 * NSEQ;

    for (int r = tid; r < 128; r += 256) {
        const float bv = bout[m0 + r];
#pragma unroll
        for (int c = 0; c < 16; ++c) brep[r * 16 + c] = bv;
    }
    __syncthreads();

    wmma::fragment<wmma::accumulator, 16, 16, 16, float> acc[4][2];
#pragma unroll
    for (int mi = 0; mi < 4; ++mi)
#pragma unroll
        for (int ni = 0; ni < 2; ++ni)
            wmma::load_matrix_sync(acc[mi][ni],
                                   &brep[(wm * 64 + mi * 16) * 16], 16,
                                   wmma::mem_row_major);

#pragma unroll 1
    for (int kk = 0; kk < 256; kk += 32) {
        __syncthreads();
        // stage A (fp16 hi/lo): 128 rows x 32 halves
#pragma unroll
        for (int it = 0; it < 2; ++it) {
            const int idx = tid + it * 256;
            const int row = idx >> 2, c4 = idx & 3;
            const size_t go = (size_t)(m0 + row) * 256 + kk + c4 * 8;
            const int    so = row * SMS2 + c4 * 8;
            *reinterpret_cast<uint4*>(&sAh[so]) = *reinterpret_cast<const uint4*>(Ah + go);
            *reinterpret_cast<uint4*>(&sAl[so]) = *reinterpret_cast<const uint4*>(Al + go);
        }
        // stage B: 32 k-rows x 128 p halves (pure copies)
#pragma unroll
        for (int it = 0; it < 2; ++it) {
            const int idx = tid + it * 256;      // 0..511
            const int row = idx >> 4, c8 = idx & 15;
            const size_t go = (size_t)(kk + row) * NSEQ + p0 + c8 * 8;
            const int    so = row * OVS + c8 * 8;
            *reinterpret_cast<uint4*>(&sBh[so]) = *reinterpret_cast<const uint4*>(Xh + go);
            *reinterpret_cast<uint4*>(&sBl[so]) = *reinterpret_cast<const uint4*>(Xl + go);
        }
        __syncthreads();

#pragma unroll
        for (int k2 = 0; k2 < 2; ++k2) {
            wmma::fragment<wmma::matrix_a, 16, 16, 16, __half, wmma::row_major> fah[4], fal[4];
            wmma::fragment<wmma::matrix_b, 16, 16, 16, __half, wmma::row_major> fbh[2], fbl[2];
#pragma unroll
            for (int mi = 0; mi < 4; ++mi) {
                const int ro = (wm * 64 + mi * 16) * SMS2 + k2 * 16;
                wmma::load_matrix_sync(fah[mi], &sAh[ro], SMS2);
                wmma::load_matrix_sync(fal[mi], &sAl[ro], SMS2);
            }
#pragma unroll
            for (int ni = 0; ni < 2; ++ni) {
                const int co = (k2 * 16) * OVS + wn * 32 + ni * 16;
                wmma::load_matrix_sync(fbh[ni], &sBh[co], OVS);
                wmma::load_matrix_sync(fbl[ni], &sBl[co], OVS);
            }
#pragma unroll
            for (int mi = 0; mi < 4; ++mi)
#pragma unroll
                for (int ni = 0; ni < 2; ++ni) {
                    wmma::mma_sync(acc[mi][ni], fah[mi], fbh[ni], acc[mi][ni]);
                    wmma::mma_sync(acc[mi][ni], fah[mi], fbl[ni], acc[mi][ni]);
                    wmma::mma_sync(acc[mi][ni], fal[mi], fbh[ni], acc[mi][ni]);
                }
        }
    }

    float* C = out + (size_t)g * 256 * NSEQ;
#pragma unroll
    for (int mi = 0; mi < 4; ++mi)
#pragma unroll
        for (int ni = 0; ni < 2; ++ni)
            wmma::store_matrix_sync(
                C + (size_t)(m0 + wm * 64 + mi * 16) * NSEQ + p0 + wn * 32 + ni * 16,
                acc[mi][ni], NSEQ, wmma::mem_row_major);
}

// ---------------------------------------------------------------------------
extern "C" void kernel_launch(void* const* d_in, const int* in_sizes, int n_in,
                              void* d_out, int out_size)
{
    const float* x    = (const float*)d_in[0];
    const float* Wq   = (const float*)d_in[1];
    const float* Wkv  = (const float*)d_in[2];
    const float* Wout = (const float*)d_in[3];
    const float* bout = (const float*)d_in[4];
    float* out = (float*)d_out;
    (void)in_sizes; (void)n_in; (void)out_size;

    convert_x   <<<dim3(256, 2), 256>>>(x);
    gram_kernel <<<dim3(GSP, 3, 2), 256>>>();
    gram_reduce <<<dim3(256, 2), 256>>>();
    sq_kernel   <<<dim3(512, 2), 256>>>(Wq);
    simp_kernel <<<dim3(4, 16), 256>>>(Wkv);
    softmax_kernel<<<dim3(64, 16), 64>>>();
    u_kernel    <<<dim3(4, 16), 256>>>(Wkv);
    w2_kernel   <<<dim3(256, 2), 256>>>(Wout);
    final_kernel<<<dim3(NSEQ / 128, 2, 2), 256>>>(bout, out);
}